// round 12
// baseline (speedup 1.0000x reference)
#include <cuda_runtime.h>
#include <cuda_bf16.h>
#include <cstdint>

#define N_NODES_MAX 50000
#define E_MAX       620000
#define D_FEAT      128
#define HIDDEN      256
#define K_DIM       256   // 2*D_FEAT

// Scratch (device globals — no allocation allowed)
__device__ float g_h[N_NODES_MAX * K_DIM];   // 51.2 MB  tf32 [mean | nodes]
__device__ float g_W[K_DIM * HIDDEN];        // 0.26 MB  tf32 W
__device__ int   g_deg[N_NODES_MAX];         // receiver degrees
__device__ int   g_off[N_NODES_MAX];         // CSR offsets (exclusive scan)
__device__ int   g_pos[E_MAX];               // per-edge slot within receiver
__device__ int   g_csr[E_MAX];               // sender idx grouped by receiver

__device__ __forceinline__ float to_tf32(float x) {
    float y;
    asm("cvt.rna.tf32.f32 %0, %1;" : "=f"(y) : "f"(x));
    return y;
}

// ---------------------------------------------------------------------------
// Kernel 1: prep — zero degrees, convert nodes -> g_h[:,128:], W -> g_W
// ---------------------------------------------------------------------------
__global__ void prep_kernel(const float* __restrict__ nodes,
                            const float* __restrict__ W, int M) {
    const int tid    = blockIdx.x * blockDim.x + threadIdx.x;
    const int stride = gridDim.x * blockDim.x;

    for (int i = tid; i < M; i += stride) g_deg[i] = 0;

    const int nf4 = (M * D_FEAT) / 4;
    const float4* n4 = reinterpret_cast<const float4*>(nodes);
    for (int i = tid; i < nf4; i += stride) {
        int row = i >> 5;            // 32 float4 per node row
        int c   = (i & 31) << 2;
        float4 v = n4[i];
        float4 t = make_float4(to_tf32(v.x), to_tf32(v.y),
                               to_tf32(v.z), to_tf32(v.w));
        *reinterpret_cast<float4*>(g_h + (size_t)row * K_DIM + D_FEAT + c) = t;
    }

    const int w4 = (K_DIM * HIDDEN) / 4;
    const float4* W4 = reinterpret_cast<const float4*>(W);
    float4* gW4 = reinterpret_cast<float4*>(g_W);
    for (int i = tid; i < w4; i += stride) {
        float4 v = W4[i];
        gW4[i] = make_float4(to_tf32(v.x), to_tf32(v.y),
                             to_tf32(v.z), to_tf32(v.w));
    }
}

// ---------------------------------------------------------------------------
// Kernel 2: degrees + per-edge slot claim (single returning atomic per edge)
// ---------------------------------------------------------------------------
__global__ void degree_kernel(const int* __restrict__ receivers, int E) {
    int e = blockIdx.x * blockDim.x + threadIdx.x;
    if (e < E) g_pos[e] = atomicAdd(&g_deg[receivers[e]], 1);
}

// ---------------------------------------------------------------------------
// Kernel 3: single-block exclusive scan g_deg -> g_off.
// ---------------------------------------------------------------------------
__global__ __launch_bounds__(1024)
void scan_kernel(int M) {
    __shared__ int s[1024];
    const int chunk = (M + 1023) >> 10;
    const int begin = threadIdx.x * chunk;
    const int end   = min(begin + chunk, M);

    int sum = 0;
    for (int i = begin; i < end; i++) sum += g_deg[i];
    s[threadIdx.x] = sum;
    __syncthreads();
#pragma unroll
    for (int off = 1; off < 1024; off <<= 1) {
        int t = (threadIdx.x >= off) ? s[threadIdx.x - off] : 0;
        __syncthreads();
        s[threadIdx.x] += t;
        __syncthreads();
    }
    int run = s[threadIdx.x] - sum;   // exclusive prefix of this chunk
    for (int i = begin; i < end; i++) {
        int d = g_deg[i];
        g_off[i] = run;
        run += d;
    }
}

// ---------------------------------------------------------------------------
// Kernel 4: fill CSR — NO atomics: csr[off[r] + pos[e]] = senders[e]
// ---------------------------------------------------------------------------
__global__ void fill_kernel(const int* __restrict__ senders,
                            const int* __restrict__ receivers, int E) {
    int e = blockIdx.x * blockDim.x + threadIdx.x;
    if (e >= E) return;
    int r = receivers[e];
    g_csr[g_off[r] + g_pos[e]] = senders[e];
}

// ---------------------------------------------------------------------------
// Kernel 5: gather — one warp per node, 4-way unrolled. Plain L2 loads,
// no atomics. Fuses mean + tf32 + write to g_h[:, :128].
// ---------------------------------------------------------------------------
__global__ void gather_kernel(const float* __restrict__ nodes, int M) {
    int warp = (blockIdx.x * blockDim.x + threadIdx.x) >> 5;
    int lane = threadIdx.x & 31;
    if (warp >= M) return;

    int deg  = g_deg[warp];
    int base = g_off[warp];
    const float4* n4 = reinterpret_cast<const float4*>(nodes);

    float4 a0 = make_float4(0.f, 0.f, 0.f, 0.f);
    float4 a1 = make_float4(0.f, 0.f, 0.f, 0.f);
    float4 a2 = make_float4(0.f, 0.f, 0.f, 0.f);
    float4 a3 = make_float4(0.f, 0.f, 0.f, 0.f);

    int j = 0;
    for (; j + 4 <= deg; j += 4) {
        int s0 = g_csr[base + j];
        int s1 = g_csr[base + j + 1];
        int s2 = g_csr[base + j + 2];
        int s3 = g_csr[base + j + 3];
        float4 v0 = n4[(size_t)s0 * 32 + lane];
        float4 v1 = n4[(size_t)s1 * 32 + lane];
        float4 v2 = n4[(size_t)s2 * 32 + lane];
        float4 v3 = n4[(size_t)s3 * 32 + lane];
        a0.x += v0.x; a0.y += v0.y; a0.z += v0.z; a0.w += v0.w;
        a1.x += v1.x; a1.y += v1.y; a1.z += v1.z; a1.w += v1.w;
        a2.x += v2.x; a2.y += v2.y; a2.z += v2.z; a2.w += v2.w;
        a3.x += v3.x; a3.y += v3.y; a3.z += v3.z; a3.w += v3.w;
    }
    for (; j < deg; j++) {
        int s0 = g_csr[base + j];
        float4 v0 = n4[(size_t)s0 * 32 + lane];
        a0.x += v0.x; a0.y += v0.y; a0.z += v0.z; a0.w += v0.w;
    }

    float rcp = 1.0f / fmaxf((float)deg, 1.0f);
    float sx = (a0.x + a1.x) + (a2.x + a3.x);
    float sy = (a0.y + a1.y) + (a2.y + a3.y);
    float sz = (a0.z + a1.z) + (a2.z + a3.z);
    float sw = (a0.w + a1.w) + (a2.w + a3.w);
    float4 t = make_float4(to_tf32(sx * rcp), to_tf32(sy * rcp),
                           to_tf32(sz * rcp), to_tf32(sw * rcp));
    *reinterpret_cast<float4*>(g_h + (size_t)warp * K_DIM + lane * 4) = t;
}

// ---------------------------------------------------------------------------
// Kernel 6: GEMM C = relu(g_h @ g_W + b). EXACT round-10 configuration
// (plain launch_bounds(256), regs ~78, 3 CTAs/SM — measured 58.6us).
// ---------------------------------------------------------------------------
#define BM 128
#define BN 64
#define BK 32
#define ASTR 36
#define BSTR 72
#define NTILES (K_DIM / BK)

#define AS_FLOATS (BM * ASTR)
#define BS_FLOATS (BK * BSTR)
#define SMEM_FLOATS (2 * (AS_FLOATS + BS_FLOATS))
#define SMEM_BYTES (SMEM_FLOATS * 4)

extern __shared__ float smem_dyn[];

__global__ __launch_bounds__(256)
void gemm_kernel(const float* __restrict__ bias,
                 float* __restrict__ C,
                 int M) {
    float* As = smem_dyn;
    float* Bs = smem_dyn + 2 * AS_FLOATS;

    const int tid  = threadIdx.x;
    const int lane = tid & 31;
    const int wid  = tid >> 5;
    const int warp_m = wid >> 1;
    const int warp_n = wid & 1;
    const int gid = lane >> 2;
    const int tig = lane & 3;

    const int block_m = blockIdx.x * BM;
    const int block_n = blockIdx.y * BN;

    const uint32_t s_base = (uint32_t)__cvta_generic_to_shared(smem_dyn);

    auto load_tiles = [&](int t, int stage) {
        const uint32_t a_base = s_base + (uint32_t)(stage * AS_FLOATS) * 4u;
        const uint32_t b_base = s_base + (uint32_t)(2 * AS_FLOATS + stage * BS_FLOATS) * 4u;
#pragma unroll
        for (int i = 0; i < 4; i++) {
            int idx = tid + i * 256;
            int row = idx >> 3;
            int c4  = (idx & 7) << 2;
            int gm  = block_m + row;
            int gmc = gm < M ? gm : 0;
            const float* src = g_h + (size_t)gmc * K_DIM + t * BK + c4;
            uint32_t dst = a_base + (uint32_t)(row * ASTR + c4) * 4u;
            int sz = (gm < M) ? 16 : 0;
            asm volatile("cp.async.cg.shared.global [%0], [%1], 16, %2;\n"
                         :: "r"(dst), "l"(src), "r"(sz));
        }
#pragma unroll
        for (int i = 0; i < 2; i++) {
            int idx = tid + i * 256;
            int row = idx >> 4;
            int c4  = (idx & 15) << 2;
            const float* src = g_W + (size_t)(t * BK + row) * HIDDEN + block_n + c4;
            uint32_t dst = b_base + (uint32_t)(row * BSTR + c4) * 4u;
            asm volatile("cp.async.cg.shared.global [%0], [%1], 16;\n"
                         :: "r"(dst), "l"(src));
        }
    };

    float c[2][4][4];
#pragma unroll
    for (int mt = 0; mt < 2; mt++)
#pragma unroll
        for (int nt = 0; nt < 4; nt++)
#pragma unroll
            for (int i = 0; i < 4; i++) c[mt][nt][i] = 0.f;

    load_tiles(0, 0);
    asm volatile("cp.async.commit_group;\n" ::: "memory");

    for (int t = 0; t < NTILES; t++) {
        if (t + 1 < NTILES) {
            load_tiles(t + 1, (t + 1) & 1);
            asm volatile("cp.async.commit_group;\n" ::: "memory");
            asm volatile("cp.async.wait_group 1;\n" ::: "memory");
        } else {
            asm volatile("cp.async.wait_group 0;\n" ::: "memory");
        }
        __syncthreads();

        const float* Ab = As + (t & 1) * AS_FLOATS;
        const float* Bb = Bs + (t & 1) * BS_FLOATS;

#pragma unroll
        for (int kk = 0; kk < 4; kk++) {
            const int k = kk * 8;
            uint32_t a[2][4], b[4][2];
#pragma unroll
            for (int mt = 0; mt < 2; mt++) {
                int r = warp_m * 32 + mt * 16 + gid;
                a[mt][0] = __float_as_uint(Ab[(r    ) * ASTR + k + tig    ]);
                a[mt][1] = __float_as_uint(Ab[(r + 8) * ASTR + k + tig    ]);
                a[mt][2] = __float_as_uint(Ab[(r    ) * ASTR + k + tig + 4]);
                a[mt][3] = __float_as_uint(Ab[(r + 8) * ASTR + k + tig + 4]);
            }
#pragma unroll
            for (int nt = 0; nt < 4; nt++) {
                int col = warp_n * 32 + nt * 8 + gid;
                b[nt][0] = __float_as_uint(Bb[(k + tig    ) * BSTR + col]);
                b[nt][1] = __float_as_uint(Bb[(k + tig + 4) * BSTR + col]);
            }
#pragma unroll
            for (int mt = 0; mt < 2; mt++)
#pragma unroll
                for (int nt = 0; nt < 4; nt++) {
                    asm volatile(
                        "mma.sync.aligned.m16n8k8.row.col.f32.tf32.tf32.f32 "
                        "{%0,%1,%2,%3}, {%4,%5,%6,%7}, {%8,%9}, {%0,%1,%2,%3};"
                        : "+f"(c[mt][nt][0]), "+f"(c[mt][nt][1]),
                          "+f"(c[mt][nt][2]), "+f"(c[mt][nt][3])
                        : "r"(a[mt][0]), "r"(a[mt][1]), "r"(a[mt][2]), "r"(a[mt][3]),
                          "r"(b[nt][0]), "r"(b[nt][1]));
                }
        }
        __syncthreads();
    }

#pragma unroll
    for (int nt = 0; nt < 4; nt++) {
        int col = block_n + warp_n * 32 + nt * 8 + 2 * tig;
        float b0 = bias[col];
        float b1 = bias[col + 1];
#pragma unroll
        for (int mt = 0; mt < 2; mt++) {
            int r0 = block_m + warp_m * 32 + mt * 16 + gid;
            if (r0 < M) {
                float2 o;
                o.x = fmaxf(c[mt][nt][0] + b0, 0.f);
                o.y = fmaxf(c[mt][nt][1] + b1, 0.f);
                *reinterpret_cast<float2*>(C + (size_t)r0 * HIDDEN + col) = o;
            }
            int r1 = r0 + 8;
            if (r1 < M) {
                float2 o;
                o.x = fmaxf(c[mt][nt][2] + b0, 0.f);
                o.y = fmaxf(c[mt][nt][3] + b1, 0.f);
                *reinterpret_cast<float2*>(C + (size_t)r1 * HIDDEN + col) = o;
            }
        }
    }
}

// ---------------------------------------------------------------------------
extern "C" void kernel_launch(void* const* d_in, const int* in_sizes, int n_in,
                              void* d_out, int out_size) {
    const float* nodes     = (const float*)d_in[0];
    const int*   senders   = (const int*)d_in[1];
    const int*   receivers = (const int*)d_in[2];
    const float* W         = (const float*)d_in[3];
    const float* bias      = (const float*)d_in[4];
    float*       out       = (float*)d_out;

    const int M = in_sizes[0] / D_FEAT;   // 50000
    const int E = in_sizes[1];            // 600000

    // 1) prep: zero degrees + tf32 pre-conversion of nodes & W
    prep_kernel<<<2048, 256>>>(nodes, W, M);

    // 2) CSR build: degree+slot -> single-block scan -> atomic-free fill
    degree_kernel<<<(E + 255) / 256, 256>>>(receivers, E);
    scan_kernel<<<1, 1024>>>(M);
    fill_kernel<<<(E + 255) / 256, 256>>>(senders, receivers, E);

    // 3) gather + mean + tf32 into g_h[:, :128]
    gather_kernel<<<(M * 32 + 255) / 256, 256>>>(nodes, M);

    // 4) GEMM
    static bool attr_set = false;
    if (!attr_set) {
        cudaFuncSetAttribute(gemm_kernel,
                             cudaFuncAttributeMaxDynamicSharedMemorySize,
                             SMEM_BYTES);
        attr_set = true;
    }
    dim3 grid((M + BM - 1) / BM, HIDDEN / BN);
    gemm_kernel<<<grid, 256, SMEM_BYTES>>>(bias, out, M);
}

// round 13
// speedup vs baseline: 1.3576x; 1.3576x over previous
#include <cuda_runtime.h>
#include <cuda_bf16.h>
#include <cstdint>

#define N_NODES_MAX 50000
#define E_MAX       620000
#define D_FEAT      128
#define HIDDEN      256
#define K_DIM       256   // 2*D_FEAT

// Scratch (device globals — no allocation allowed)
__device__ float g_h[N_NODES_MAX * K_DIM];   // 51.2 MB  tf32 [mean | nodes]
__device__ float g_W[K_DIM * HIDDEN];        // 0.26 MB  tf32 W
__device__ int   g_deg[N_NODES_MAX];         // receiver degrees
__device__ int   g_off[N_NODES_MAX];         // CSR offsets (exclusive scan)
__device__ int   g_pos[E_MAX];               // per-edge slot within receiver
__device__ int   g_csr[E_MAX];               // sender idx grouped by receiver
__device__ int   g_part[512];                // scan block partials

__device__ __forceinline__ float to_tf32(float x) {
    float y;
    asm("cvt.rna.tf32.f32 %0, %1;" : "=f"(y) : "f"(x));
    return y;
}

// ---------------------------------------------------------------------------
// Kernel 1: prep — zero degrees, convert nodes -> g_h[:,128:], W -> g_W
// ---------------------------------------------------------------------------
__global__ void prep_kernel(const float* __restrict__ nodes,
                            const float* __restrict__ W, int M) {
    const int tid    = blockIdx.x * blockDim.x + threadIdx.x;
    const int stride = gridDim.x * blockDim.x;

    for (int i = tid; i < M; i += stride) g_deg[i] = 0;

    const int nf4 = (M * D_FEAT) / 4;
    const float4* n4 = reinterpret_cast<const float4*>(nodes);
    for (int i = tid; i < nf4; i += stride) {
        int row = i >> 5;            // 32 float4 per node row
        int c   = (i & 31) << 2;
        float4 v = n4[i];
        float4 t = make_float4(to_tf32(v.x), to_tf32(v.y),
                               to_tf32(v.z), to_tf32(v.w));
        *reinterpret_cast<float4*>(g_h + (size_t)row * K_DIM + D_FEAT + c) = t;
    }

    const int w4 = (K_DIM * HIDDEN) / 4;
    const float4* W4 = reinterpret_cast<const float4*>(W);
    float4* gW4 = reinterpret_cast<float4*>(g_W);
    for (int i = tid; i < w4; i += stride) {
        float4 v = W4[i];
        gW4[i] = make_float4(to_tf32(v.x), to_tf32(v.y),
                             to_tf32(v.z), to_tf32(v.w));
    }
}

// ---------------------------------------------------------------------------
// Kernel 2: degrees + per-edge slot claim (single returning atomic per edge)
// ---------------------------------------------------------------------------
__global__ void degree_kernel(const int* __restrict__ receivers, int E) {
    int e = blockIdx.x * blockDim.x + threadIdx.x;
    if (e < E) g_pos[e] = atomicAdd(&g_deg[receivers[e]], 1);
}

// ---------------------------------------------------------------------------
// Kernels 3a/3b/3c: COALESCED two-level exclusive scan g_deg -> g_off.
// (Round-10 proven version; lane-contiguous indexing -> 1 line per warp-load.
// The single-block chunked scan was a 32x uncoalesced regression.)
// ---------------------------------------------------------------------------
__global__ void scan1_kernel(int M) {
    __shared__ int s[256];
    int i = blockIdx.x * 256 + threadIdx.x;
    int v = (i < M) ? g_deg[i] : 0;
    s[threadIdx.x] = v;
    __syncthreads();
#pragma unroll
    for (int off = 1; off < 256; off <<= 1) {
        int t = (threadIdx.x >= off) ? s[threadIdx.x - off] : 0;
        __syncthreads();
        s[threadIdx.x] += t;
        __syncthreads();
    }
    if (i < M) g_off[i] = s[threadIdx.x] - v;             // exclusive in-block
    if (threadIdx.x == 255) g_part[blockIdx.x] = s[255];  // block total
}

__global__ void scan2_kernel(int nblocks) {
    __shared__ int s[512];
    int v = (threadIdx.x < nblocks) ? g_part[threadIdx.x] : 0;
    s[threadIdx.x] = v;
    __syncthreads();
#pragma unroll
    for (int off = 1; off < 512; off <<= 1) {
        int t = (threadIdx.x >= off) ? s[threadIdx.x - off] : 0;
        __syncthreads();
        s[threadIdx.x] += t;
        __syncthreads();
    }
    if (threadIdx.x < nblocks) g_part[threadIdx.x] = s[threadIdx.x] - v;
}

__global__ void scan3_kernel(int M) {
    int i = blockIdx.x * 256 + threadIdx.x;
    if (i < M) g_off[i] += g_part[blockIdx.x];
}

// ---------------------------------------------------------------------------
// Kernel 4: fill CSR — NO atomics: csr[off[r] + pos[e]] = senders[e]
// ---------------------------------------------------------------------------
__global__ void fill_kernel(const int* __restrict__ senders,
                            const int* __restrict__ receivers, int E) {
    int e = blockIdx.x * blockDim.x + threadIdx.x;
    if (e >= E) return;
    int r = receivers[e];
    g_csr[g_off[r] + g_pos[e]] = senders[e];
}

// ---------------------------------------------------------------------------
// Kernel 5: gather — one warp per node, 4-way unrolled. Lane-coalesced
// 512B row loads, no atomics. Fuses mean + tf32 + write to g_h[:, :128].
// ---------------------------------------------------------------------------
__global__ void gather_kernel(const float* __restrict__ nodes, int M) {
    int warp = (blockIdx.x * blockDim.x + threadIdx.x) >> 5;
    int lane = threadIdx.x & 31;
    if (warp >= M) return;

    int deg  = g_deg[warp];
    int base = g_off[warp];
    const float4* n4 = reinterpret_cast<const float4*>(nodes);

    float4 a0 = make_float4(0.f, 0.f, 0.f, 0.f);
    float4 a1 = make_float4(0.f, 0.f, 0.f, 0.f);
    float4 a2 = make_float4(0.f, 0.f, 0.f, 0.f);
    float4 a3 = make_float4(0.f, 0.f, 0.f, 0.f);

    int j = 0;
    for (; j + 4 <= deg; j += 4) {
        int s0 = g_csr[base + j];
        int s1 = g_csr[base + j + 1];
        int s2 = g_csr[base + j + 2];
        int s3 = g_csr[base + j + 3];
        float4 v0 = n4[(size_t)s0 * 32 + lane];
        float4 v1 = n4[(size_t)s1 * 32 + lane];
        float4 v2 = n4[(size_t)s2 * 32 + lane];
        float4 v3 = n4[(size_t)s3 * 32 + lane];
        a0.x += v0.x; a0.y += v0.y; a0.z += v0.z; a0.w += v0.w;
        a1.x += v1.x; a1.y += v1.y; a1.z += v1.z; a1.w += v1.w;
        a2.x += v2.x; a2.y += v2.y; a2.z += v2.z; a2.w += v2.w;
        a3.x += v3.x; a3.y += v3.y; a3.z += v3.z; a3.w += v3.w;
    }
    for (; j < deg; j++) {
        int s0 = g_csr[base + j];
        float4 v0 = n4[(size_t)s0 * 32 + lane];
        a0.x += v0.x; a0.y += v0.y; a0.z += v0.z; a0.w += v0.w;
    }

    float rcp = 1.0f / fmaxf((float)deg, 1.0f);
    float sx = (a0.x + a1.x) + (a2.x + a3.x);
    float sy = (a0.y + a1.y) + (a2.y + a3.y);
    float sz = (a0.z + a1.z) + (a2.z + a3.z);
    float sw = (a0.w + a1.w) + (a2.w + a3.w);
    float4 t = make_float4(to_tf32(sx * rcp), to_tf32(sy * rcp),
                           to_tf32(sz * rcp), to_tf32(sw * rcp));
    *reinterpret_cast<float4*>(g_h + (size_t)warp * K_DIM + lane * 4) = t;
}

// ---------------------------------------------------------------------------
// Kernel 6: GEMM C = relu(g_h @ g_W + b). EXACT round-10 configuration
// (plain launch_bounds(256), regs ~78, 3 CTAs/SM — measured 58.6us).
// ---------------------------------------------------------------------------
#define BM 128
#define BN 64
#define BK 32
#define ASTR 36
#define BSTR 72
#define NTILES (K_DIM / BK)

#define AS_FLOATS (BM * ASTR)
#define BS_FLOATS (BK * BSTR)
#define SMEM_FLOATS (2 * (AS_FLOATS + BS_FLOATS))
#define SMEM_BYTES (SMEM_FLOATS * 4)

extern __shared__ float smem_dyn[];

__global__ __launch_bounds__(256)
void gemm_kernel(const float* __restrict__ bias,
                 float* __restrict__ C,
                 int M) {
    float* As = smem_dyn;
    float* Bs = smem_dyn + 2 * AS_FLOATS;

    const int tid  = threadIdx.x;
    const int lane = tid & 31;
    const int wid  = tid >> 5;
    const int warp_m = wid >> 1;
    const int warp_n = wid & 1;
    const int gid = lane >> 2;
    const int tig = lane & 3;

    const int block_m = blockIdx.x * BM;
    const int block_n = blockIdx.y * BN;

    const uint32_t s_base = (uint32_t)__cvta_generic_to_shared(smem_dyn);

    auto load_tiles = [&](int t, int stage) {
        const uint32_t a_base = s_base + (uint32_t)(stage * AS_FLOATS) * 4u;
        const uint32_t b_base = s_base + (uint32_t)(2 * AS_FLOATS + stage * BS_FLOATS) * 4u;
#pragma unroll
        for (int i = 0; i < 4; i++) {
            int idx = tid + i * 256;
            int row = idx >> 3;
            int c4  = (idx & 7) << 2;
            int gm  = block_m + row;
            int gmc = gm < M ? gm : 0;
            const float* src = g_h + (size_t)gmc * K_DIM + t * BK + c4;
            uint32_t dst = a_base + (uint32_t)(row * ASTR + c4) * 4u;
            int sz = (gm < M) ? 16 : 0;
            asm volatile("cp.async.cg.shared.global [%0], [%1], 16, %2;\n"
                         :: "r"(dst), "l"(src), "r"(sz));
        }
#pragma unroll
        for (int i = 0; i < 2; i++) {
            int idx = tid + i * 256;
            int row = idx >> 4;
            int c4  = (idx & 15) << 2;
            const float* src = g_W + (size_t)(t * BK + row) * HIDDEN + block_n + c4;
            uint32_t dst = b_base + (uint32_t)(row * BSTR + c4) * 4u;
            asm volatile("cp.async.cg.shared.global [%0], [%1], 16;\n"
                         :: "r"(dst), "l"(src));
        }
    };

    float c[2][4][4];
#pragma unroll
    for (int mt = 0; mt < 2; mt++)
#pragma unroll
        for (int nt = 0; nt < 4; nt++)
#pragma unroll
            for (int i = 0; i < 4; i++) c[mt][nt][i] = 0.f;

    load_tiles(0, 0);
    asm volatile("cp.async.commit_group;\n" ::: "memory");

    for (int t = 0; t < NTILES; t++) {
        if (t + 1 < NTILES) {
            load_tiles(t + 1, (t + 1) & 1);
            asm volatile("cp.async.commit_group;\n" ::: "memory");
            asm volatile("cp.async.wait_group 1;\n" ::: "memory");
        } else {
            asm volatile("cp.async.wait_group 0;\n" ::: "memory");
        }
        __syncthreads();

        const float* Ab = As + (t & 1) * AS_FLOATS;
        const float* Bb = Bs + (t & 1) * BS_FLOATS;

#pragma unroll
        for (int kk = 0; kk < 4; kk++) {
            const int k = kk * 8;
            uint32_t a[2][4], b[4][2];
#pragma unroll
            for (int mt = 0; mt < 2; mt++) {
                int r = warp_m * 32 + mt * 16 + gid;
                a[mt][0] = __float_as_uint(Ab[(r    ) * ASTR + k + tig    ]);
                a[mt][1] = __float_as_uint(Ab[(r + 8) * ASTR + k + tig    ]);
                a[mt][2] = __float_as_uint(Ab[(r    ) * ASTR + k + tig + 4]);
                a[mt][3] = __float_as_uint(Ab[(r + 8) * ASTR + k + tig + 4]);
            }
#pragma unroll
            for (int nt = 0; nt < 4; nt++) {
                int col = warp_n * 32 + nt * 8 + gid;
                b[nt][0] = __float_as_uint(Bb[(k + tig    ) * BSTR + col]);
                b[nt][1] = __float_as_uint(Bb[(k + tig + 4) * BSTR + col]);
            }
#pragma unroll
            for (int mt = 0; mt < 2; mt++)
#pragma unroll
                for (int nt = 0; nt < 4; nt++) {
                    asm volatile(
                        "mma.sync.aligned.m16n8k8.row.col.f32.tf32.tf32.f32 "
                        "{%0,%1,%2,%3}, {%4,%5,%6,%7}, {%8,%9}, {%0,%1,%2,%3};"
                        : "+f"(c[mt][nt][0]), "+f"(c[mt][nt][1]),
                          "+f"(c[mt][nt][2]), "+f"(c[mt][nt][3])
                        : "r"(a[mt][0]), "r"(a[mt][1]), "r"(a[mt][2]), "r"(a[mt][3]),
                          "r"(b[nt][0]), "r"(b[nt][1]));
                }
        }
        __syncthreads();
    }

#pragma unroll
    for (int nt = 0; nt < 4; nt++) {
        int col = block_n + warp_n * 32 + nt * 8 + 2 * tig;
        float b0 = bias[col];
        float b1 = bias[col + 1];
#pragma unroll
        for (int mt = 0; mt < 2; mt++) {
            int r0 = block_m + warp_m * 32 + mt * 16 + gid;
            if (r0 < M) {
                float2 o;
                o.x = fmaxf(c[mt][nt][0] + b0, 0.f);
                o.y = fmaxf(c[mt][nt][1] + b1, 0.f);
                *reinterpret_cast<float2*>(C + (size_t)r0 * HIDDEN + col) = o;
            }
            int r1 = r0 + 8;
            if (r1 < M) {
                float2 o;
                o.x = fmaxf(c[mt][nt][2] + b0, 0.f);
                o.y = fmaxf(c[mt][nt][3] + b1, 0.f);
                *reinterpret_cast<float2*>(C + (size_t)r1 * HIDDEN + col) = o;
            }
        }
    }
}

// ---------------------------------------------------------------------------
extern "C" void kernel_launch(void* const* d_in, const int* in_sizes, int n_in,
                              void* d_out, int out_size) {
    const float* nodes     = (const float*)d_in[0];
    const int*   senders   = (const int*)d_in[1];
    const int*   receivers = (const int*)d_in[2];
    const float* W         = (const float*)d_in[3];
    const float* bias      = (const float*)d_in[4];
    float*       out       = (float*)d_out;

    const int M = in_sizes[0] / D_FEAT;   // 50000
    const int E = in_sizes[1];            // 600000

    // 1) prep: zero degrees + tf32 pre-conversion of nodes & W
    prep_kernel<<<2048, 256>>>(nodes, W, M);

    // 2) CSR build: degree+slot -> coalesced 3-kernel scan -> atomic-free fill
    degree_kernel<<<(E + 255) / 256, 256>>>(receivers, E);
    int nb = (M + 255) / 256;             // 196 for M=50000 (<=512 required)
    scan1_kernel<<<nb, 256>>>(M);
    scan2_kernel<<<1, 512>>>(nb);
    scan3_kernel<<<nb, 256>>>(M);
    fill_kernel<<<(E + 255) / 256, 256>>>(senders, receivers, E);

    // 3) gather + mean + tf32 into g_h[:, :128]
    gather_kernel<<<(M * 32 + 255) / 256, 256>>>(nodes, M);

    // 4) GEMM
    static bool attr_set = false;
    if (!attr_set) {
        cudaFuncSetAttribute(gemm_kernel,
                             cudaFuncAttributeMaxDynamicSharedMemorySize,
                             SMEM_BYTES);
        attr_set = true;
    }
    dim3 grid((M + BM - 1) / BM, HIDDEN / BN);
    gemm_kernel<<<grid, 256, SMEM_BYTES>>>(bias, out, M);
}